// round 9
// baseline (speedup 1.0000x reference)
#include <cuda_runtime.h>
#include <math.h>
#include <stdint.h>

#define NB 4096
#define ND 1024
#define NH 2048
#define NC 1000
#define NT 819200
#define NF 32
#define NCPAD 1024

// ---------------- scratch (static device globals; no allocation) ----------------
__device__ float g_means[NB * NF];
__device__ float g_combined[(size_t)NB * ND];
__device__ float g_hidden[(size_t)NB * NH];
__device__ float g_logits[(size_t)NB * NC];
__device__ float g_scalar[NB];
__device__ float g_row_lv[NB];
__device__ float g_row_acc[NB];
__device__ unsigned int g_maxbits[4];   // 0: combined, 1: W1, 2: hidden, 3: W2
// packed int8 limbs (mma fragment order)
__device__ char g_a1_l1[(size_t)NB * ND];
__device__ char g_a1_l2[(size_t)NB * ND];
__device__ char g_w1_l1[(size_t)NH * ND];
__device__ char g_w1_l2[(size_t)NH * ND];
__device__ char g_a2_l1[(size_t)NB * NH];
__device__ char g_a2_l2[(size_t)NB * NH];
__device__ char g_w2_l1[(size_t)NCPAD * NH];
__device__ char g_w2_l2[(size_t)NCPAD * NH];

// ---------------- helpers ----------------
__device__ __forceinline__ uint32_t smem_u32(const void* p) {
    uint32_t a;
    asm("{ .reg .u64 t; cvta.to.shared.u64 t, %1; cvt.u32.u64 %0, t; }" : "=r"(a) : "l"(p));
    return a;
}
__device__ __forceinline__ void cp16(uint32_t dst, const void* src) {
    asm volatile("cp.async.cg.shared.global [%0], [%1], 16;" :: "r"(dst), "l"(src) : "memory");
}
__device__ __forceinline__ void cp_commit() { asm volatile("cp.async.commit_group;" ::: "memory"); }

__device__ __forceinline__ void imma32(int* d, const uint32_t* a, const uint32_t* b) {
    asm volatile(
        "mma.sync.aligned.m16n8k32.row.col.s32.s8.s8.s32 "
        "{%0,%1,%2,%3}, {%4,%5,%6,%7}, {%8,%9}, {%0,%1,%2,%3};"
        : "+r"(d[0]), "+r"(d[1]), "+r"(d[2]), "+r"(d[3])
        : "r"(a[0]), "r"(a[1]), "r"(a[2]), "r"(a[3]), "r"(b[0]), "r"(b[1]));
}
__device__ __forceinline__ void lds128(uint32_t* r, uint32_t a) {
    asm volatile("ld.shared.v4.b32 {%0,%1,%2,%3}, [%4];"
                 : "=r"(r[0]), "=r"(r[1]), "=r"(r[2]), "=r"(r[3]) : "r"(a));
}
__device__ __forceinline__ void lds64(uint32_t* r, uint32_t a) {
    asm volatile("ld.shared.v2.b32 {%0,%1}, [%2];" : "=r"(r[0]), "=r"(r[1]) : "r"(a));
}

// quantize 4 values -> two packed limb words.  x ~= (l1 + l2/254) * max/127
__device__ __forceinline__ void pack4(float x0, float x1, float x2, float x3, float s,
                                      uint32_t& w1, uint32_t& w2) {
    const int a0 = __float2int_rn(x0 * s), a1 = __float2int_rn(x1 * s);
    const int a2 = __float2int_rn(x2 * s), a3 = __float2int_rn(x3 * s);
    const int b0 = __float2int_rn((x0 * s - (float)a0) * 254.0f);
    const int b1 = __float2int_rn((x1 * s - (float)a1) * 254.0f);
    const int b2 = __float2int_rn((x2 * s - (float)a2) * 254.0f);
    const int b3 = __float2int_rn((x3 * s - (float)a3) * 254.0f);
    w1 = (a0 & 255) | ((a1 & 255) << 8) | ((a2 & 255) << 16) | ((a3 & 255) << 24);
    w2 = (b0 & 255) | ((b1 & 255) << 8) | ((b2 & 255) << 16) | ((b3 & 255) << 24);
}
// word offset for packed A fragment (m16n8k32), element (r, c) with c%4==0
__device__ __forceinline__ size_t waoff8(int r, int c, int K) {
    const size_t tile = (size_t)(r >> 4) * (K >> 5) + (c >> 5);
    const int lane = ((r & 7) << 2) + ((c >> 2) & 3);
    const int reg  = ((r >> 3) & 1) + (((c >> 4) & 1) << 1);
    return tile * 128 + lane * 4 + reg;
}
// word offset for packed B fragment (m16n8k32), element (n, k) with k%4==0
__device__ __forceinline__ size_t wboff8(int n, int k, int K) {
    const size_t tile = (size_t)(n >> 3) * (K >> 5) + (k >> 5);
    const int lane = ((n & 7) << 2) + ((k >> 2) & 3);
    const int reg  = (k >> 4) & 1;
    return tile * 64 + lane * 2 + reg;
}

// ---------------- misc small kernels ----------------
__global__ void init_max_kernel() {
    if (threadIdx.x < 4) g_maxbits[threadIdx.x] = 0u;
}

__global__ void __launch_bounds__(256) maxabs_kernel(const float* __restrict__ x,
                                                     size_t n, int slot) {
    float m = 0.0f;
    for (size_t i = (size_t)blockIdx.x * 256 + threadIdx.x; i < n; i += (size_t)gridDim.x * 256)
        m = fmaxf(m, fabsf(x[i]));
#pragma unroll
    for (int o = 16; o > 0; o >>= 1) m = fmaxf(m, __shfl_xor_sync(0xffffffffu, m, o));
    if ((threadIdx.x & 31) == 0) atomicMax(&g_maxbits[slot], __float_as_uint(m));
}

// quantize row-major activation [M,K] -> packed A-fragment limbs
__global__ void __launch_bounds__(256) quantA_kernel(const float* __restrict__ src,
                                                     int K, char* __restrict__ l1t,
                                                     char* __restrict__ l2t,
                                                     int slot, size_t nquads) {
    const size_t idx = (size_t)blockIdx.x * 256 + threadIdx.x;
    if (idx >= nquads) return;
    const int kq4 = K >> 2;
    const int r  = (int)(idx / kq4);
    const int kq = (int)(idx % kq4) << 2;
    const float4 v = *(const float4*)(src + (size_t)r * K + kq);
    const float mx = fmaxf(__uint_as_float(g_maxbits[slot]), 1e-30f);
    const float s = 127.0f / mx;
    uint32_t w1, w2;
    pack4(v.x, v.y, v.z, v.w, s, w1, w2);
    const size_t o = waoff8(r, kq, K);
    ((uint32_t*)l1t)[o] = w1;
    ((uint32_t*)l2t)[o] = w2;
}

// quantize row-major weight [rows,K] (padded to prows) -> packed B-fragment limbs
__global__ void __launch_bounds__(256) quantB_kernel(const float* __restrict__ W,
                                                     int rows, int K, int prows,
                                                     char* __restrict__ l1t,
                                                     char* __restrict__ l2t, int slot) {
    const size_t idx = (size_t)blockIdx.x * 256 + threadIdx.x;
    const size_t tot = (size_t)prows * (K >> 2);
    if (idx >= tot) return;
    const int kq4 = K >> 2;
    const int n  = (int)(idx / kq4);
    const int kq = (int)(idx % kq4) << 2;
    float4 v = make_float4(0.f, 0.f, 0.f, 0.f);
    if (n < rows) v = *(const float4*)(W + (size_t)n * K + kq);
    const float mx = fmaxf(__uint_as_float(g_maxbits[slot]), 1e-30f);
    const float s = 127.0f / mx;
    uint32_t w1, w2;
    pack4(v.x, v.y, v.z, v.w, s, w1, w2);
    const size_t o = wboff8(n, kq, K);
    ((uint32_t*)l1t)[o] = w1;
    ((uint32_t*)l2t)[o] = w2;
}

// ---------------- segment mean ----------------
__global__ void __launch_bounds__(256) seg_mean_kernel(const float* __restrict__ var_flat,
                                                       const int* __restrict__ seg) {
    __shared__ int s_bounds[2];
    __shared__ float red[8][32];
    const int b = blockIdx.x;
    const int tid = threadIdx.x;
    if (tid < 2) {
        const int v = b + tid;
        int lo = 0, hi = NT;
        while (lo < hi) {
            int mid = (lo + hi) >> 1;
            if (seg[mid] < v) lo = mid + 1; else hi = mid;
        }
        s_bounds[tid] = lo;
    }
    __syncthreads();
    const int start = s_bounds[0];
    const int end   = s_bounds[1];
    const int f = tid & 31;
    const int w = tid >> 5;
    float acc = 0.0f;
    for (int r = start + w; r < end; r += 8)
        acc += var_flat[(size_t)r * NF + f];
    red[w][f] = acc;
    __syncthreads();
    if (w == 0) {
        float s = 0.0f;
#pragma unroll
        for (int i = 0; i < 8; i++) s += red[i][f];
        const float cnt = fmaxf((float)(end - start), 1.0f);
        g_means[b * NF + f] = s / cnt;
    }
}

// ---------------- comb GEMM (K=32): combined = means@Wv^T + bv + feature (fp32) + max ----------------
__global__ void __launch_bounds__(256, 2) sgemm_comb(const float* __restrict__ A,
                                                     const float* __restrict__ W,
                                                     const float* __restrict__ bias,
                                                     const float* __restrict__ addend,
                                                     float* __restrict__ C) {
    __shared__ float As[NF][128];
    __shared__ float Bs[NF][128];
    const int bm  = blockIdx.y * 128;
    const int bn  = blockIdx.x * 128;
    const int tid = threadIdx.x;
    const int tx  = tid & 15;
    const int ty  = tid >> 4;

#pragma unroll
    for (int it = 0; it < 4; it++) {
        const int idx = tid + it * 256;
        const int r = idx >> 3;
        const int q = idx & 7;
        const float4 av = *(const float4*)(A + (size_t)(bm + r) * NF + q * 4);
        const float4 wv = *(const float4*)(W + (size_t)(bn + r) * NF + q * 4);
        As[q * 4 + 0][r] = av.x; As[q * 4 + 1][r] = av.y;
        As[q * 4 + 2][r] = av.z; As[q * 4 + 3][r] = av.w;
        Bs[q * 4 + 0][r] = wv.x; Bs[q * 4 + 1][r] = wv.y;
        Bs[q * 4 + 2][r] = wv.z; Bs[q * 4 + 3][r] = wv.w;
    }

    float acc[8][8];
    const float4 bv0 = *(const float4*)(bias + bn + tx * 8);
    const float4 bv1 = *(const float4*)(bias + bn + tx * 8 + 4);
#pragma unroll
    for (int i = 0; i < 8; i++) {
        const int m = bm + ty * 8 + i;
        const float4 a0 = *(const float4*)(addend + (size_t)m * ND + bn + tx * 8);
        const float4 a1 = *(const float4*)(addend + (size_t)m * ND + bn + tx * 8 + 4);
        acc[i][0] = a0.x + bv0.x; acc[i][1] = a0.y + bv0.y;
        acc[i][2] = a0.z + bv0.z; acc[i][3] = a0.w + bv0.w;
        acc[i][4] = a1.x + bv1.x; acc[i][5] = a1.y + bv1.y;
        acc[i][6] = a1.z + bv1.z; acc[i][7] = a1.w + bv1.w;
    }
    __syncthreads();

#pragma unroll
    for (int k = 0; k < NF; k++) {
        float a[8], bb[8];
#pragma unroll
        for (int i = 0; i < 8; i++) a[i] = As[k][ty * 8 + i];
#pragma unroll
        for (int j = 0; j < 8; j++) bb[j] = Bs[k][tx * 8 + j];
#pragma unroll
        for (int i = 0; i < 8; i++)
#pragma unroll
            for (int j = 0; j < 8; j++) acc[i][j] += a[i] * bb[j];
    }

    float lmax = 0.0f;
#pragma unroll
    for (int i = 0; i < 8; i++) {
        const int m = bm + ty * 8 + i;
#pragma unroll
        for (int j = 0; j < 8; j++) lmax = fmaxf(lmax, fabsf(acc[i][j]));
        *(float4*)(C + (size_t)m * ND + bn + tx * 8)     = make_float4(acc[i][0], acc[i][1], acc[i][2], acc[i][3]);
        *(float4*)(C + (size_t)m * ND + bn + tx * 8 + 4) = make_float4(acc[i][4], acc[i][5], acc[i][6], acc[i][7]);
    }
#pragma unroll
    for (int o = 16; o > 0; o >>= 1) lmax = fmaxf(lmax, __shfl_xor_sync(0xffffffffu, lmax, o));
    if ((tid & 31) == 0) atomicMax(&g_maxbits[0], __float_as_uint(lmax));
}

// ---------------- int8 2-limb tensor-core GEMM (NT), CTA 128x64, BK=64, 3-stage, occ=2 ----------------
// stage: [A l1 8KB][A l2 8KB][B l1 4KB][B l2 4KB] = 24KB
#define STAGE_BYTES 24576

#define LOADC(stg, ck) do {                                                           \
        const uint32_t _d0 = sbase + (uint32_t)(stg) * (uint32_t)STAGE_BYTES;         \
        _Pragma("unroll")                                                             \
        for (int _i = 0; _i < 6; _i++) {                                              \
            const int _u = tid + _i * 256;                                            \
            const char* _src; uint32_t _dst;                                          \
            if (_u < 1024) {                                                          \
                const int _lb = _u >> 9, _w = _u & 511;                               \
                const int _mt = _w >> 6, _rem = _w & 63;                              \
                _src = (_lb ? Al2 : Al1)                                              \
                     + ((size_t)(mtile0 + _mt) * KB32 + 2 * (ck)) * 512 + _rem * 16;  \
                _dst = _d0 + _lb * 8192 + _mt * 1024 + _rem * 16;                     \
            } else {                                                                  \
                const int _v = _u - 1024;                                             \
                const int _lb = _v >> 8, _w = _v & 255;                               \
                const int _nt = _w >> 5, _rem = _w & 31;                              \
                _src = (_lb ? Bl2 : Bl1)                                              \
                     + ((size_t)(ntile0 + _nt) * KB32 + 2 * (ck)) * 256 + _rem * 16;  \
                _dst = _d0 + 16384 + _lb * 4096 + _nt * 512 + _rem * 16;              \
            }                                                                         \
            cp16(_dst, _src);                                                         \
        }                                                                             \
        cp_commit();                                                                  \
    } while (0)

template <int KDIM, bool IS_G1>
__global__ void __launch_bounds__(256, 2) imma_gemm(
    const char* __restrict__ Al1, const char* __restrict__ Al2,
    const char* __restrict__ Bl1, const char* __restrict__ Bl2,
    const float* __restrict__ bias,
    float* __restrict__ Crow, int sa, int sb) {
    constexpr int KB32 = KDIM / 32;
    constexpr int NCH  = KDIM / 64;
    extern __shared__ __align__(16) char smem[];
    const int tid  = threadIdx.x;
    const int lane = tid & 31;
    const int wrp  = tid >> 5;
    const int warp_m = (wrp & 1) * 64;     // 2 warps along M (128)
    const int warp_n = (wrp >> 1) * 16;    // 4 warps along N (64)
    const int mtW = (wrp & 1) * 4;
    const int ntW = (wrp >> 1) * 2;
    const int bm = blockIdx.y * 128;
    const int bn = blockIdx.x * 64;
    const int mtile0 = blockIdx.y * 8;
    const int ntile0 = blockIdx.x * 8;
    const uint32_t sbase = smem_u32(smem);

    int acc11[4][2][4], accX[4][2][4];
#pragma unroll
    for (int a = 0; a < 4; a++)
#pragma unroll
        for (int b = 0; b < 2; b++)
#pragma unroll
            for (int c = 0; c < 4; c++) { acc11[a][b][c] = 0; accX[a][b][c] = 0; }

    LOADC(0, 0);
    LOADC(1, 1);

#pragma unroll 1
    for (int ch = 0; ch < NCH; ch++) {
        if (ch + 2 < NCH) {
            LOADC((ch + 2) % 3, ch + 2);
            asm volatile("cp.async.wait_group 2;" ::: "memory");
        } else if (ch + 1 < NCH) {
            asm volatile("cp.async.wait_group 1;" ::: "memory");
        } else {
            asm volatile("cp.async.wait_group 0;" ::: "memory");
        }
        __syncthreads();
        const uint32_t stg = sbase + (uint32_t)(ch % 3) * (uint32_t)STAGE_BYTES;
#pragma unroll
        for (int kt = 0; kt < 2; kt++) {
            uint32_t af1[4][4], af2[4][4];
#pragma unroll
            for (int mt = 0; mt < 4; mt++) {
                const uint32_t adr = stg + (mtW + mt) * 1024 + kt * 512 + lane * 16;
                lds128(af1[mt], adr);
                lds128(af2[mt], adr + 8192);
            }
            uint32_t bf1[2][2], bf2[2][2];
#pragma unroll
            for (int nt = 0; nt < 2; nt++) {
                const uint32_t badr = stg + 16384 + (ntW + nt) * 512 + kt * 256 + lane * 8;
                lds64(bf1[nt], badr);
                lds64(bf2[nt], badr + 4096);
            }
#pragma unroll
            for (int nt = 0; nt < 2; nt++) {
#pragma unroll
                for (int mt = 0; mt < 4; mt++) imma32(acc11[mt][nt], af1[mt], bf1[nt]);
#pragma unroll
                for (int mt = 0; mt < 4; mt++) imma32(accX[mt][nt], af1[mt], bf2[nt]);
#pragma unroll
                for (int mt = 0; mt < 4; mt++) imma32(accX[mt][nt], af2[mt], bf1[nt]);
            }
        }
        __syncthreads();
    }

    // epilogue
    const float ma = fmaxf(__uint_as_float(g_maxbits[sa]), 1e-30f);
    const float mb = fmaxf(__uint_as_float(g_maxbits[sb]), 1e-30f);
    const float rs = ma * mb / 16129.0f;     // 127*127
    const float inv254 = 1.0f / 254.0f;
    const int g  = lane >> 2;
    const int tg = lane & 3;
    float lmax = 0.0f;
#pragma unroll
    for (int mt = 0; mt < 4; mt++) {
#pragma unroll
        for (int nt = 0; nt < 2; nt++) {
            const int col0 = bn + warp_n + nt * 8 + tg * 2;
            const int row0 = bm + warp_m + mt * 16 + g;
#pragma unroll
            for (int half = 0; half < 2; half++) {
                const int row = row0 + half * 8;
                float v0 = ((float)acc11[mt][nt][half * 2 + 0]
                            + (float)accX[mt][nt][half * 2 + 0] * inv254) * rs;
                float v1 = ((float)acc11[mt][nt][half * 2 + 1]
                            + (float)accX[mt][nt][half * 2 + 1] * inv254) * rs;
                if (IS_G1) {
                    v0 = fmaxf(v0 + __ldg(&bias[col0]), 0.0f);
                    v1 = fmaxf(v1 + __ldg(&bias[col0 + 1]), 0.0f);
                    Crow[(size_t)row * NH + col0]     = v0;
                    Crow[(size_t)row * NH + col0 + 1] = v1;
                    lmax = fmaxf(lmax, fmaxf(v0, v1));
                } else {
                    if (col0 < NC)
                        Crow[(size_t)row * NC + col0] = v0 + __ldg(&bias[col0]);
                    if (col0 + 1 < NC)
                        Crow[(size_t)row * NC + col0 + 1] = v1 + __ldg(&bias[col0 + 1]);
                }
            }
        }
    }
    if (IS_G1) {
#pragma unroll
        for (int o = 16; o > 0; o >>= 1) lmax = fmaxf(lmax, __shfl_xor_sync(0xffffffffu, lmax, o));
        if (lane == 0) atomicMax(&g_maxbits[2], __float_as_uint(lmax));
    }
}

// ---------------- scalar head ----------------
__global__ void __launch_bounds__(256) scalar_kernel(const float* __restrict__ Ws,
                                                     const float* __restrict__ bs) {
    const int warp = threadIdx.x >> 5;
    const int lane = threadIdx.x & 31;
    const int b = blockIdx.x * 8 + warp;
    const float* hrow = g_hidden + (size_t)b * NH;
    float acc = 0.0f;
    for (int k = lane; k < NH; k += 32) acc += hrow[k] * __ldg(&Ws[k]);
#pragma unroll
    for (int o = 16; o > 0; o >>= 1) acc += __shfl_down_sync(0xffffffffu, acc, o);
    if (lane == 0) g_scalar[b] = acc + bs[0];
}

// ---------------- per-row logsumexp + argmax ----------------
__global__ void __launch_bounds__(256) loss_row_kernel(const int* __restrict__ target) {
    __shared__ float sval[256];
    __shared__ int   sidx[256];
    __shared__ float ssum[256];
    const int b = blockIdx.x;
    const int tid = threadIdx.x;
    const float* row = g_logits + (size_t)b * NC;

    float mval = -3.402823466e38f;
    int midx = 0;
    for (int c = tid; c < NC; c += 256) {
        const float v = row[c];
        if (v > mval) { mval = v; midx = c; }
    }
    sval[tid] = mval; sidx[tid] = midx;
    __syncthreads();
    for (int s = 128; s > 0; s >>= 1) {
        if (tid < s) {
            const float v2 = sval[tid + s];
            const int   i2 = sidx[tid + s];
            if (v2 > sval[tid] || (v2 == sval[tid] && i2 < sidx[tid])) {
                sval[tid] = v2; sidx[tid] = i2;
            }
        }
        __syncthreads();
    }
    const float maxv = sval[0];
    const int   amax = sidx[0];

    float lsum = 0.0f;
    for (int c = tid; c < NC; c += 256) {
        const float d = row[c] - maxv;
        if (d > -20.0f) lsum += __expf(d);
    }
    ssum[tid] = lsum;
    __syncthreads();
    for (int s = 128; s > 0; s >>= 1) {
        if (tid < s) ssum[tid] += ssum[tid + s];
        __syncthreads();
    }
    if (tid == 0) {
        const int t = target[b];
        g_row_lv[b]  = maxv + logf(ssum[0]) - row[t];
        g_row_acc[b] = (amax == t) ? 1.0f : 0.0f;
    }
}

// ---------------- final reduce ----------------
__global__ void __launch_bounds__(1024) final_kernel(const float* __restrict__ target_scalar,
                                                     float* __restrict__ out) {
    __shared__ float s_lv[1024];
    __shared__ float s_ac[1024];
    __shared__ float s_sq[1024];
    const int tid = threadIdx.x;
    float lv = 0.0f, ac = 0.0f, sq = 0.0f;
    for (int b = tid; b < NB; b += 1024) {
        lv += g_row_lv[b];
        ac += g_row_acc[b];
        const float d = g_scalar[b] - target_scalar[b];
        sq += d * d;
    }
    s_lv[tid] = lv; s_ac[tid] = ac; s_sq[tid] = sq;
    __syncthreads();
    for (int s = 512; s > 0; s >>= 1) {
        if (tid < s) {
            s_lv[tid] += s_lv[tid + s];
            s_ac[tid] += s_ac[tid + s];
            s_sq[tid] += s_sq[tid + s];
        }
        __syncthreads();
    }
    if (tid == 0) {
        const float lvm  = s_lv[0] / (float)NB;
        const float sqm  = s_sq[0] / (float)NB;
        const float accm = s_ac[0] / (float)NB;
        out[0] = lvm + sqm;
        out[1] = lvm;
        out[2] = sqm;
        out[3] = accm;
    }
}

// ---------------- launch ----------------
extern "C" void kernel_launch(void* const* d_in, const int* in_sizes, int n_in,
                              void* d_out, int out_size) {
    const float* feature  = (const float*)d_in[0];
    const float* var_flat = (const float*)d_in[1];
    const int*   seg      = (const int*)d_in[2];
    const int*   target_v = (const int*)d_in[3];
    const float* target_s = (const float*)d_in[4];
    const float* Wv       = (const float*)d_in[5];
    const float* bv       = (const float*)d_in[6];
    const float* W1       = (const float*)d_in[7];
    const float* b1       = (const float*)d_in[8];
    const float* W2       = (const float*)d_in[9];
    const float* b2       = (const float*)d_in[10];
    const float* Ws       = (const float*)d_in[11];
    const float* bs       = (const float*)d_in[12];
    float* out = (float*)d_out;

    float *p_means, *p_comb, *p_hid, *p_log;
    char *p_a1l1, *p_a1l2, *p_w1l1, *p_w1l2, *p_a2l1, *p_a2l2, *p_w2l1, *p_w2l2;
    cudaGetSymbolAddress((void**)&p_means, g_means);
    cudaGetSymbolAddress((void**)&p_comb,  g_combined);
    cudaGetSymbolAddress((void**)&p_hid,   g_hidden);
    cudaGetSymbolAddress((void**)&p_log,   g_logits);
    cudaGetSymbolAddress((void**)&p_a1l1,  g_a1_l1);
    cudaGetSymbolAddress((void**)&p_a1l2,  g_a1_l2);
    cudaGetSymbolAddress((void**)&p_w1l1,  g_w1_l1);
    cudaGetSymbolAddress((void**)&p_w1l2,  g_w1_l2);
    cudaGetSymbolAddress((void**)&p_a2l1,  g_a2_l1);
    cudaGetSymbolAddress((void**)&p_a2l2,  g_a2_l2);
    cudaGetSymbolAddress((void**)&p_w2l1,  g_w2_l1);
    cudaGetSymbolAddress((void**)&p_w2l2,  g_w2_l2);

    const int SMEM_GEMM = 3 * STAGE_BYTES;  // 73728
    cudaFuncSetAttribute(imma_gemm<1024, true>,
                         cudaFuncAttributeMaxDynamicSharedMemorySize, SMEM_GEMM);
    cudaFuncSetAttribute(imma_gemm<2048, false>,
                         cudaFuncAttributeMaxDynamicSharedMemorySize, SMEM_GEMM);

    // 0) zero the max slots
    init_max_kernel<<<1, 32>>>();

    // 1) ragged per-segment mean
    seg_mean_kernel<<<NB, 256>>>(var_flat, seg);

    // 2) weight maxes + quantize into packed B-fragment limbs
    maxabs_kernel<<<512, 256>>>(W1, (size_t)NH * ND, 1);
    maxabs_kernel<<<512, 256>>>(W2, (size_t)NC * NH, 3);
    quantB_kernel<<<(int)(((size_t)NH * ND / 4 + 255) / 256), 256>>>(
        W1, NH, ND, NH, p_w1l1, p_w1l2, 1);
    quantB_kernel<<<(int)(((size_t)NCPAD * NH / 4 + 255) / 256), 256>>>(
        W2, NC, NH, NCPAD, p_w2l1, p_w2l2, 3);

    // 3) combined = means@Wv^T + bv + feature (fp32 + max), then quantize
    sgemm_comb<<<dim3(ND / 128, NB / 128), 256>>>(p_means, Wv, bv, feature, p_comb);
    quantA_kernel<<<(int)(((size_t)NB * ND / 4 + 255) / 256), 256>>>(
        p_comb, ND, p_a1l1, p_a1l2, 0, (size_t)NB * ND / 4);

    // 4) hidden = relu(combined@W1^T + b1)  [imma s8 2-limb], writes fp32 + max
    imma_gemm<1024, true><<<dim3(NH / 64, NB / 128), 256, SMEM_GEMM>>>(
        p_a1l1, p_a1l2, p_w1l1, p_w1l2, b1, p_hid, 0, 1);

    // 5) quantize hidden, then logits = hidden@W2^T + b2
    quantA_kernel<<<(int)(((size_t)NB * NH / 4 + 255) / 256), 256>>>(
        p_hid, NH, p_a2l1, p_a2l2, 2, (size_t)NB * NH / 4);
    imma_gemm<2048, false><<<dim3(NCPAD / 64, NB / 128), 256, SMEM_GEMM>>>(
        p_a2l1, p_a2l2, p_w2l1, p_w2l2, b2, p_log, 2, 3);

    // 6) scalar head
    scalar_kernel<<<NB / 8, 256>>>(Ws, bs);

    // 7) per-row softmax stats
    loss_row_kernel<<<NB, 256>>>(target_v);

    // 8) final reduce
    final_kernel<<<1, 1024>>>(target_s, out);
}

// round 10
// speedup vs baseline: 3.3442x; 3.3442x over previous
#include <cuda_runtime.h>
#include <cuda_fp16.h>
#include <math.h>
#include <stdint.h>

#define NB 4096
#define ND 1024
#define NH 2048
#define NC 1000
#define NT 819200
#define NF 32
#define NCPAD 1024

// ---------------- scratch (static device globals; no allocation) ----------------
__device__ float  g_means[NB * NF];
__device__ __half g_a1_hi[(size_t)NB * ND];
__device__ __half g_a1_lo[(size_t)NB * ND];   // lo limbs pre-scaled by 2048
__device__ __half g_w1_hi[(size_t)NH * ND];
__device__ __half g_w1_lo[(size_t)NH * ND];
__device__ __half g_a2_hi[(size_t)NB * NH];
__device__ __half g_a2_lo[(size_t)NB * NH];
__device__ __half g_w2_hi[(size_t)NCPAD * NH];
__device__ __half g_w2_lo[(size_t)NCPAD * NH];
__device__ float  g_hidden[(size_t)NB * NH];
__device__ float  g_logits[(size_t)NB * NC];
__device__ float  g_scalar[NB];
__device__ float  g_row_lv[NB];
__device__ float  g_row_acc[NB];

#define LO_SCALE 2048.0f
#define INV_LO_SCALE (1.0f / 2048.0f)

// ---------------- helpers ----------------
__device__ __forceinline__ uint32_t smem_u32(const void* p) {
    uint32_t a;
    asm("{ .reg .u64 t; cvta.to.shared.u64 t, %1; cvt.u32.u64 %0, t; }" : "=r"(a) : "l"(p));
    return a;
}
__device__ __forceinline__ void cp16(uint32_t dst, const void* src) {
    asm volatile("cp.async.cg.shared.global [%0], [%1], 16;" :: "r"(dst), "l"(src) : "memory");
}
__device__ __forceinline__ void cp_commit() { asm volatile("cp.async.commit_group;" ::: "memory"); }

// fp32-accumulate MMA (hi*hi product)
__device__ __forceinline__ void mma16(float* d, const uint32_t* a, const uint32_t* b) {
    asm volatile(
        "mma.sync.aligned.m16n8k16.row.col.f32.f16.f16.f32 "
        "{%0,%1,%2,%3}, {%4,%5,%6,%7}, {%8,%9}, {%0,%1,%2,%3};"
        : "+f"(d[0]), "+f"(d[1]), "+f"(d[2]), "+f"(d[3])
        : "r"(a[0]), "r"(a[1]), "r"(a[2]), "r"(a[3]), "r"(b[0]), "r"(b[1]));
}
// fp16-accumulate MMA (cross terms; both share one accumulator pair)
__device__ __forceinline__ void mma16h(uint32_t* d, const uint32_t* a, const uint32_t* b) {
    asm volatile(
        "mma.sync.aligned.m16n8k16.row.col.f16.f16.f16.f16 "
        "{%0,%1}, {%2,%3,%4,%5}, {%6,%7}, {%0,%1};"
        : "+r"(d[0]), "+r"(d[1])
        : "r"(a[0]), "r"(a[1]), "r"(a[2]), "r"(a[3]), "r"(b[0]), "r"(b[1]));
}
__device__ __forceinline__ void lds128(uint32_t* r, uint32_t a) {
    asm volatile("ld.shared.v4.b32 {%0,%1,%2,%3}, [%4];"
                 : "=r"(r[0]), "=r"(r[1]), "=r"(r[2]), "=r"(r[3]) : "r"(a));
}
__device__ __forceinline__ void lds64(uint32_t* r, uint32_t a) {
    asm volatile("ld.shared.v2.b32 {%0,%1}, [%2];" : "=r"(r[0]), "=r"(r[1]) : "r"(a));
}

// packed fp16 A-fragment offset (m16n8k16) for element (r, c) of M x K: fp16 units
__device__ __forceinline__ size_t aoff16(int r, int c, int K) {
    const size_t tile = (size_t)(r >> 4) * (K >> 4) + (c >> 4);
    const int lane = ((r & 7) << 2) + ((c >> 1) & 3);
    const int reg  = ((r >> 3) & 1) + (((c >> 3) & 1) << 1);
    return tile * 256 + (size_t)((lane << 2) + reg) * 2 + (c & 1);
}
// packed fp16 B-fragment offset (m16n8k16) for element (n, k) of N x K
__device__ __forceinline__ size_t boff16(int n, int k, int K) {
    const size_t tile = (size_t)(n >> 3) * (K >> 4) + (k >> 4);
    const int lane = ((n & 7) << 2) + ((k >> 1) & 3);
    const int reg  = (k >> 3) & 1;
    return tile * 128 + (size_t)((lane << 1) + reg) * 2 + (k & 1);
}
// hi = fp16(v), lo = fp16((v - hi) * 2048)  (power-of-2 scale keeps cross products normal-range)
__device__ __forceinline__ __half2 split_pair(float v0, float v1, __half2& lo) {
    const __half h0 = __float2half_rn(v0);
    const __half h1 = __float2half_rn(v1);
    lo = __halves2half2(__float2half_rn((v0 - __half2float(h0)) * LO_SCALE),
                        __float2half_rn((v1 - __half2float(h1)) * LO_SCALE));
    return __halves2half2(h0, h1);
}

// ---------------- segment mean ----------------
__global__ void __launch_bounds__(256) seg_mean_kernel(const float* __restrict__ var_flat,
                                                       const int* __restrict__ seg) {
    __shared__ int s_bounds[2];
    __shared__ float red[8][32];
    const int b = blockIdx.x;
    const int tid = threadIdx.x;
    if (tid < 2) {
        const int v = b + tid;
        int lo = 0, hi = NT;
        while (lo < hi) {
            int mid = (lo + hi) >> 1;
            if (seg[mid] < v) lo = mid + 1; else hi = mid;
        }
        s_bounds[tid] = lo;
    }
    __syncthreads();
    const int start = s_bounds[0];
    const int end   = s_bounds[1];
    const int f = tid & 31;
    const int w = tid >> 5;
    float acc = 0.0f;
    for (int r = start + w; r < end; r += 8)
        acc += var_flat[(size_t)r * NF + f];
    red[w][f] = acc;
    __syncthreads();
    if (w == 0) {
        float s = 0.0f;
#pragma unroll
        for (int i = 0; i < 8; i++) s += red[i][f];
        const float cnt = fmaxf((float)(end - start), 1.0f);
        g_means[b * NF + f] = s / cnt;
    }
}

// ---------------- comb GEMM (K=32, fully resident): combined -> packed fp16 hi/lo ----------------
__global__ void __launch_bounds__(256, 2) sgemm_comb(const float* __restrict__ A,
                                                     const float* __restrict__ W,
                                                     const float* __restrict__ bias,
                                                     const float* __restrict__ addend,
                                                     __half* __restrict__ Phi,
                                                     __half* __restrict__ Plo) {
    __shared__ float As[NF][128];
    __shared__ float Bs[NF][128];
    const int bm  = blockIdx.y * 128;
    const int bn  = blockIdx.x * 128;
    const int tid = threadIdx.x;
    const int tx  = tid & 15;
    const int ty  = tid >> 4;

#pragma unroll
    for (int it = 0; it < 4; it++) {
        const int idx = tid + it * 256;
        const int r = idx >> 3;
        const int q = idx & 7;
        const float4 av = *(const float4*)(A + (size_t)(bm + r) * NF + q * 4);
        const float4 wv = *(const float4*)(W + (size_t)(bn + r) * NF + q * 4);
        As[q * 4 + 0][r] = av.x; As[q * 4 + 1][r] = av.y;
        As[q * 4 + 2][r] = av.z; As[q * 4 + 3][r] = av.w;
        Bs[q * 4 + 0][r] = wv.x; Bs[q * 4 + 1][r] = wv.y;
        Bs[q * 4 + 2][r] = wv.z; Bs[q * 4 + 3][r] = wv.w;
    }

    float acc[8][8];
    const float4 bv0 = *(const float4*)(bias + bn + tx * 8);
    const float4 bv1 = *(const float4*)(bias + bn + tx * 8 + 4);
#pragma unroll
    for (int i = 0; i < 8; i++) {
        const int m = bm + ty * 8 + i;
        const float4 a0 = *(const float4*)(addend + (size_t)m * ND + bn + tx * 8);
        const float4 a1 = *(const float4*)(addend + (size_t)m * ND + bn + tx * 8 + 4);
        acc[i][0] = a0.x + bv0.x; acc[i][1] = a0.y + bv0.y;
        acc[i][2] = a0.z + bv0.z; acc[i][3] = a0.w + bv0.w;
        acc[i][4] = a1.x + bv1.x; acc[i][5] = a1.y + bv1.y;
        acc[i][6] = a1.z + bv1.z; acc[i][7] = a1.w + bv1.w;
    }
    __syncthreads();

#pragma unroll
    for (int k = 0; k < NF; k++) {
        float a[8], bb[8];
#pragma unroll
        for (int i = 0; i < 8; i++) a[i] = As[k][ty * 8 + i];
#pragma unroll
        for (int j = 0; j < 8; j++) bb[j] = Bs[k][tx * 8 + j];
#pragma unroll
        for (int i = 0; i < 8; i++)
#pragma unroll
            for (int j = 0; j < 8; j++) acc[i][j] += a[i] * bb[j];
    }

#pragma unroll
    for (int i = 0; i < 8; i++) {
        const int m = bm + ty * 8 + i;
#pragma unroll
        for (int j = 0; j < 8; j += 2) {
            const int n = bn + tx * 8 + j;
            __half2 lo;
            const __half2 hi = split_pair(acc[i][j], acc[i][j + 1], lo);
            const size_t o = aoff16(m, n, ND) >> 1;
            ((__half2*)Phi)[o] = hi;
            ((__half2*)Plo)[o] = lo;
        }
    }
}

// ---------------- weight split into packed fp16 B-fragment layout (rows padded) ----------------
__global__ void __launch_bounds__(256) split_b_kernel(const float* __restrict__ W,
                                                      __half* __restrict__ hi,
                                                      __half* __restrict__ lo,
                                                      int rows, int K, int prows) {
    const size_t idx = (size_t)blockIdx.x * 256 + threadIdx.x;
    const size_t tot = (size_t)prows * (K >> 1);
    if (idx >= tot) return;
    const int n = (int)(idx / (K >> 1));
    const int k = (int)(idx % (K >> 1)) * 2;
    float v0 = 0.0f, v1 = 0.0f;
    if (n < rows) {
        v0 = W[(size_t)n * K + k];
        v1 = W[(size_t)n * K + k + 1];
    }
    __half2 l;
    const __half2 h = split_pair(v0, v1, l);
    const size_t o = boff16(n, k, K) >> 1;
    ((__half2*)hi)[o] = h;
    ((__half2*)lo)[o] = l;
}

// ---------------- fp16 split GEMM (NT), CTA 128x128, BK=32, 3-stage ----------------
// hi*hi in f32 acc; cross terms (hi*lo + lo*hi) share one f16 accumulator (possible 2x rate)
#define STAGE_BYTES 32768

#define LOADC(stg, ck) do {                                                          \
        const uint32_t _d0 = sbase + (uint32_t)(stg) * (uint32_t)STAGE_BYTES;        \
        _Pragma("unroll")                                                            \
        for (int _i = 0; _i < 8; _i++) {                                             \
            const int _u = tid + _i * 256;                                           \
            const __half* _src; uint32_t _dst;                                       \
            if (_u < 1024) {                                                         \
                const int _t = _u >> 9, _w = _u & 511;                               \
                const int _mt = _w >> 6, _rem = _w & 63;                             \
                _src = (_t ? Alo : Ahi)                                              \
                     + ((size_t)(mtile0 + _mt) * KB16 + 2 * (ck)) * 256 + _rem * 8;  \
                _dst = _d0 + _t * 8192 + _mt * 1024 + _rem * 16;                     \
            } else {                                                                 \
                const int _v = _u - 1024;                                            \
                const int _t = _v >> 9, _w = _v & 511;                               \
                const int _nt = _w >> 5, _rem = _w & 31;                             \
                _src = (_t ? Blo : Bhi)                                              \
                     + ((size_t)(ntile0 + _nt) * KB16 + 2 * (ck)) * 128 + _rem * 8;  \
                _dst = _d0 + 16384 + _t * 8192 + _nt * 512 + _rem * 16;              \
            }                                                                        \
            cp16(_dst, _src);                                                        \
        }                                                                            \
        cp_commit();                                                                 \
    } while (0)

template <int KDIM, bool IS_G1>
__global__ void __launch_bounds__(256) mma_gemm(
    const __half* __restrict__ Ahi, const __half* __restrict__ Alo,
    const __half* __restrict__ Bhi, const __half* __restrict__ Blo,
    const float* __restrict__ bias,
    float* __restrict__ Crow, __half* __restrict__ Phi, __half* __restrict__ Plo) {
    constexpr int KB16 = KDIM / 16;
    constexpr int NCH  = KDIM / 32;
    extern __shared__ __align__(16) char smem[];
    const int tid  = threadIdx.x;
    const int lane = tid & 31;
    const int wrp  = tid >> 5;
    const int warp_m = (wrp & 1) * 64;     // 2 warps along M
    const int warp_n = (wrp >> 1) * 32;    // 4 warps along N
    const int mtW = (wrp & 1) * 4;
    const int ntW = (wrp >> 1) * 4;
    const int bm = blockIdx.y * 128;
    const int bn = blockIdx.x * 128;
    const int mtile0 = blockIdx.y * 8;
    const int ntile0 = blockIdx.x * 16;
    const uint32_t sbase = smem_u32(smem);

    float acc[4][4][4];
    uint32_t cx[4][4][2];
#pragma unroll
    for (int a = 0; a < 4; a++)
#pragma unroll
        for (int b = 0; b < 4; b++) {
#pragma unroll
            for (int c = 0; c < 4; c++) acc[a][b][c] = 0.0f;
            cx[a][b][0] = 0u; cx[a][b][1] = 0u;
        }

    LOADC(0, 0);
    LOADC(1, 1);

#pragma unroll 1
    for (int ch = 0; ch < NCH; ch++) {
        if (ch + 2 < NCH) {
            LOADC((ch + 2) % 3, ch + 2);
            asm volatile("cp.async.wait_group 2;" ::: "memory");
        } else if (ch + 1 < NCH) {
            asm volatile("cp.async.wait_group 1;" ::: "memory");
        } else {
            asm volatile("cp.async.wait_group 0;" ::: "memory");
        }
        __syncthreads();
        const uint32_t stg = sbase + (uint32_t)(ch % 3) * (uint32_t)STAGE_BYTES;
#pragma unroll
        for (int kt = 0; kt < 2; kt++) {
            uint32_t ah[4][4], al[4][4];
#pragma unroll
            for (int mt = 0; mt < 4; mt++) {
                const uint32_t adr = stg + (mtW + mt) * 1024 + kt * 512 + lane * 16;
                lds128(ah[mt], adr);
                lds128(al[mt], adr + 8192);
            }
            uint32_t bh[4][2], bl[4][2];
#pragma unroll
            for (int nt = 0; nt < 4; nt++) {
                const uint32_t badr = stg + 16384 + (ntW + nt) * 512 + kt * 256 + lane * 8;
                lds64(bh[nt], badr);
                lds64(bl[nt], badr + 8192);
            }
#pragma unroll
            for (int nt = 0; nt < 4; nt++) {
#pragma unroll
                for (int mt = 0; mt < 4; mt++) mma16(acc[mt][nt], ah[mt], bh[nt]);
#pragma unroll
                for (int mt = 0; mt < 4; mt++) mma16h(cx[mt][nt], ah[mt], bl[nt]);
#pragma unroll
                for (int mt = 0; mt < 4; mt++) mma16h(cx[mt][nt], al[mt], bh[nt]);
            }
        }
        __syncthreads();
    }

    // epilogue: result = f32 acc + f16 cross acc / 2048
    const int g  = lane >> 2;
    const int tg = lane & 3;
#pragma unroll
    for (int mt = 0; mt < 4; mt++) {
#pragma unroll
        for (int nt = 0; nt < 4; nt++) {
            const int col0 = bn + warp_n + nt * 8 + tg * 2;
            const int row0 = bm + warp_m + mt * 16 + g;
#pragma unroll
            for (int half = 0; half < 2; half++) {
                const int row = row0 + half * 8;
                const float2 cf = __half22float2(
                    *reinterpret_cast<const __half2*>(&cx[mt][nt][half]));
                float v0 = acc[mt][nt][half * 2 + 0] + cf.x * INV_LO_SCALE;
                float v1 = acc[mt][nt][half * 2 + 1] + cf.y * INV_LO_SCALE;
                if (IS_G1) {
                    v0 = fmaxf(v0 + __ldg(&bias[col0]), 0.0f);
                    v1 = fmaxf(v1 + __ldg(&bias[col0 + 1]), 0.0f);
                    Crow[(size_t)row * NH + col0]     = v0;
                    Crow[(size_t)row * NH + col0 + 1] = v1;
                    __half2 lo;
                    const __half2 hi = split_pair(v0, v1, lo);
                    const size_t o = aoff16(row, col0, NH) >> 1;
                    ((__half2*)Phi)[o] = hi;
                    ((__half2*)Plo)[o] = lo;
                } else {
                    if (col0 < NC)
                        Crow[(size_t)row * NC + col0] = v0 + __ldg(&bias[col0]);
                    if (col0 + 1 < NC)
                        Crow[(size_t)row * NC + col0 + 1] = v1 + __ldg(&bias[col0 + 1]);
                }
            }
        }
    }
}

// ---------------- scalar head ----------------
__global__ void __launch_bounds__(256) scalar_kernel(const float* __restrict__ Ws,
                                                     const float* __restrict__ bs) {
    const int warp = threadIdx.x >> 5;
    const int lane = threadIdx.x & 31;
    const int b = blockIdx.x * 8 + warp;
    const float* hrow = g_hidden + (size_t)b * NH;
    float acc = 0.0f;
    for (int k = lane; k < NH; k += 32) acc += hrow[k] * __ldg(&Ws[k]);
#pragma unroll
    for (int o = 16; o > 0; o >>= 1) acc += __shfl_down_sync(0xffffffffu, acc, o);
    if (lane == 0) g_scalar[b] = acc + bs[0];
}

// ---------------- per-row logsumexp + argmax ----------------
__global__ void __launch_bounds__(256) loss_row_kernel(const int* __restrict__ target) {
    __shared__ float sval[256];
    __shared__ int   sidx[256];
    __shared__ float ssum[256];
    const int b = blockIdx.x;
    const int tid = threadIdx.x;
    const float* row = g_logits + (size_t)b * NC;

    float mval = -3.402823466e38f;
    int midx = 0;
    for (int c = tid; c < NC; c += 256) {
        const float v = row[c];
        if (v > mval) { mval = v; midx = c; }
    }
    sval[tid] = mval; sidx[tid] = midx;
    __syncthreads();
    for (int s = 128; s > 0; s >>= 1) {
        if (tid < s) {
            const float v2 = sval[tid + s];
            const int   i2 = sidx[tid + s];
            if (v2 > sval[tid] || (v2 == sval[tid] && i2 < sidx[tid])) {
                sval[tid] = v2; sidx[tid] = i2;
            }
        }
        __syncthreads();
    }
    const float maxv = sval[0];
    const int   amax = sidx[0];

    float lsum = 0.0f;
    for (int c = tid; c < NC; c += 256) {
        const float d = row[c] - maxv;
        if (d > -20.0f) lsum += __expf(d);
    }
    ssum[tid] = lsum;
    __syncthreads();
    for (int s = 128; s > 0; s >>= 1) {
        if (tid < s) ssum[tid] += ssum[tid + s];
        __syncthreads();
    }
    if (tid == 0) {
        const int t = target[b];
        g_row_lv[b]  = maxv + logf(ssum[0]) - row[t];
        g_row_acc[b] = (amax == t) ? 1.0f : 0.0f;
    }
}

// ---------------- final reduce ----------------
__global__ void __launch_bounds__(1024) final_kernel(const float* __restrict__ target_scalar,
                                                     float* __restrict__ out) {
    __shared__ float s_lv[1024];
    __shared__ float s_ac[1024];
    __shared__ float s_sq[1024];
    const int tid = threadIdx.x;
    float lv = 0.0f, ac = 0.0f, sq = 0.0f;
    for (int b = tid; b < NB; b += 1024) {
        lv += g_row_lv[b];
        ac += g_row_acc[b];
        const float d = g_scalar[b] - target_scalar[b];
        sq += d * d;
    }
    s_lv[tid] = lv; s_ac[tid] = ac; s_sq[tid] = sq;
    __syncthreads();
    for (int s = 512; s > 0; s >>= 1) {
        if (tid < s) {
            s_lv[tid] += s_lv[tid + s];
            s_ac[tid] += s_ac[tid + s];
            s_sq[tid] += s_sq[tid + s];
        }
        __syncthreads();
    }
    if (tid == 0) {
        const float lvm  = s_lv[0] / (float)NB;
        const float sqm  = s_sq[0] / (float)NB;
        const float accm = s_ac[0] / (float)NB;
        out[0] = lvm + sqm;
        out[1] = lvm;
        out[2] = sqm;
        out[3] = accm;
    }
}

// ---------------- launch ----------------
extern "C" void kernel_launch(void* const* d_in, const int* in_sizes, int n_in,
                              void* d_out, int out_size) {
    const float* feature  = (const float*)d_in[0];
    const float* var_flat = (const float*)d_in[1];
    const int*   seg      = (const int*)d_in[2];
    const int*   target_v = (const int*)d_in[3];
    const float* target_s = (const float*)d_in[4];
    const float* Wv       = (const float*)d_in[5];
    const float* bv       = (const float*)d_in[6];
    const float* W1       = (const float*)d_in[7];
    const float* b1       = (const float*)d_in[8];
    const float* W2       = (const float*)d_in[9];
    const float* b2       = (const float*)d_in[10];
    const float* Ws       = (const float*)d_in[11];
    const float* bs       = (const float*)d_in[12];
    float* out = (float*)d_out;

    float *p_means, *p_hid, *p_log;
    __half *p_a1h, *p_a1l, *p_w1h, *p_w1l, *p_a2h, *p_a2l, *p_w2h, *p_w2l;
    cudaGetSymbolAddress((void**)&p_means, g_means);
    cudaGetSymbolAddress((void**)&p_a1h,   g_a1_hi);
    cudaGetSymbolAddress((void**)&p_a1l,   g_a1_lo);
    cudaGetSymbolAddress((void**)&p_w1h,   g_w1_hi);
    cudaGetSymbolAddress((void**)&p_w1l,   g_w1_lo);
    cudaGetSymbolAddress((void**)&p_a2h,   g_a2_hi);
    cudaGetSymbolAddress((void**)&p_a2l,   g_a2_lo);
    cudaGetSymbolAddress((void**)&p_w2h,   g_w2_hi);
    cudaGetSymbolAddress((void**)&p_w2l,   g_w2_lo);
    cudaGetSymbolAddress((void**)&p_hid,   g_hidden);
    cudaGetSymbolAddress((void**)&p_log,   g_logits);

    const int SMEM_GEMM = 3 * STAGE_BYTES;  // 98304
    cudaFuncSetAttribute(mma_gemm<1024, true>,
                         cudaFuncAttributeMaxDynamicSharedMemorySize, SMEM_GEMM);
    cudaFuncSetAttribute(mma_gemm<2048, false>,
                         cudaFuncAttributeMaxDynamicSharedMemorySize, SMEM_GEMM);

    // 1) ragged per-segment mean
    seg_mean_kernel<<<NB, 256>>>(var_flat, seg);

    // 2) weight splits into packed fp16 B-fragment layout
    {
        size_t n1 = (size_t)NH * ND / 2;
        split_b_kernel<<<(int)((n1 + 255) / 256), 256>>>(W1, p_w1h, p_w1l, NH, ND, NH);
        size_t n2 = (size_t)NCPAD * NH / 2;
        split_b_kernel<<<(int)((n2 + 255) / 256), 256>>>(W2, p_w2h, p_w2l, NC, NH, NCPAD);
    }

    // 3) combined = means@Wv^T + bv + feature -> packed fp16 A hi/lo
    sgemm_comb<<<dim3(ND / 128, NB / 128), 256>>>(
        p_means, Wv, bv, feature, p_a1h, p_a1l);

    // 4) hidden = relu(combined@W1^T + b1)  [fp16 split, f16-acc cross terms]
    mma_gemm<1024, true><<<dim3(NH / 128, NB / 128), 256, SMEM_GEMM>>>(
        p_a1h, p_a1l, p_w1h, p_w1l, b1, p_hid, p_a2h, p_a2l);

    // 5) logits = hidden@W2^T + b2  [fp16 split, f16-acc cross terms], N guard 1000
    mma_gemm<2048, false><<<dim3(NCPAD / 128, NB / 128), 256, SMEM_GEMM>>>(
        p_a2h, p_a2l, p_w2h, p_w2l, b2, p_log, nullptr, nullptr);

    // 6) scalar head
    scalar_kernel<<<NB / 8, 256>>>(Ws, bs);

    // 7) per-row softmax stats
    loss_row_kernel<<<NB, 256>>>(target_v);

    // 8) final reduce
    final_kernel<<<1, 1024>>>(target_s, out);
}

// round 11
// speedup vs baseline: 4.9101x; 1.4683x over previous
#include <cuda_runtime.h>
#include <cuda_fp16.h>
#include <math.h>
#include <stdint.h>

#define NB 4096
#define ND 1024
#define NH 2048
#define NC 1000
#define NT 819200
#define NF 32
#define NCPAD 1024

// ---------------- scratch (static device globals; no allocation) ----------------
__device__ float  g_means[NB * NF];
__device__ __half g_a1_hi[(size_t)NB * ND];      // combined, single fp16 limb, packed A-frag
__device__ __half g_w1_hi[(size_t)NH * ND];      // W1 hi limb, packed B-frag
__device__ __half g_w1_lo[(size_t)NH * ND];      // W1 residual limb
__device__ __half g_a2_hi[(size_t)NB * NH];      // hidden, single fp16 limb, packed A-frag
__device__ __half g_w2_hi[(size_t)NCPAD * NH];
__device__ __half g_w2_lo[(size_t)NCPAD * NH];
__device__ float  g_hidden[(size_t)NB * NH];     // row-major fp32 (scalar head)
__device__ float  g_logits[(size_t)NB * NC];
__device__ float  g_scalar[NB];
__device__ float  g_row_lv[NB];
__device__ float  g_row_acc[NB];

// ---------------- helpers ----------------
__device__ __forceinline__ uint32_t smem_u32(const void* p) {
    uint32_t a;
    asm("{ .reg .u64 t; cvta.to.shared.u64 t, %1; cvt.u32.u64 %0, t; }" : "=r"(a) : "l"(p));
    return a;
}
__device__ __forceinline__ void cp16(uint32_t dst, const void* src) {
    asm volatile("cp.async.cg.shared.global [%0], [%1], 16;" :: "r"(dst), "l"(src) : "memory");
}
__device__ __forceinline__ void cp_commit() { asm volatile("cp.async.commit_group;" ::: "memory"); }

__device__ __forceinline__ void mma16(float* d, const uint32_t* a, const uint32_t* b) {
    asm volatile(
        "mma.sync.aligned.m16n8k16.row.col.f32.f16.f16.f32 "
        "{%0,%1,%2,%3}, {%4,%5,%6,%7}, {%8,%9}, {%0,%1,%2,%3};"
        : "+f"(d[0]), "+f"(d[1]), "+f"(d[2]), "+f"(d[3])
        : "r"(a[0]), "r"(a[1]), "r"(a[2]), "r"(a[3]), "r"(b[0]), "r"(b[1]));
}
__device__ __forceinline__ void lds128(uint32_t* r, uint32_t a) {
    asm volatile("ld.shared.v4.b32 {%0,%1,%2,%3}, [%4];"
                 : "=r"(r[0]), "=r"(r[1]), "=r"(r[2]), "=r"(r[3]) : "r"(a));
}
__device__ __forceinline__ void lds64(uint32_t* r, uint32_t a) {
    asm volatile("ld.shared.v2.b32 {%0,%1}, [%2];" : "=r"(r[0]), "=r"(r[1]) : "r"(a));
}

// packed fp16 A-fragment offset (m16n8k16) for element (r, c) of M x K: fp16 units
__device__ __forceinline__ size_t aoff16(int r, int c, int K) {
    const size_t tile = (size_t)(r >> 4) * (K >> 4) + (c >> 4);
    const int lane = ((r & 7) << 2) + ((c >> 1) & 3);
    const int reg  = ((r >> 3) & 1) + (((c >> 3) & 1) << 1);
    return tile * 256 + (size_t)((lane << 2) + reg) * 2 + (c & 1);
}
// packed fp16 B-fragment offset (m16n8k16) for element (n, k) of N x K
__device__ __forceinline__ size_t boff16(int n, int k, int K) {
    const size_t tile = (size_t)(n >> 3) * (K >> 4) + (k >> 4);
    const int lane = ((n & 7) << 2) + ((k >> 1) & 3);
    const int reg  = (k >> 3) & 1;
    return tile * 128 + (size_t)((lane << 1) + reg) * 2 + (k & 1);
}
// 2-limb split for weights: hi = fp16(v), lo = fp16(v - hi)  (lo may be subnormal; OK on HW)
__device__ __forceinline__ __half2 split_pair(float v0, float v1, __half2& lo) {
    const __half h0 = __float2half_rn(v0);
    const __half h1 = __float2half_rn(v1);
    lo = __halves2half2(__float2half_rn(v0 - __half2float(h0)),
                        __float2half_rn(v1 - __half2float(h1)));
    return __halves2half2(h0, h1);
}

// ---------------- segment mean ----------------
__global__ void __launch_bounds__(256) seg_mean_kernel(const float* __restrict__ var_flat,
                                                       const int* __restrict__ seg) {
    __shared__ int s_bounds[2];
    __shared__ float red[8][32];
    const int b = blockIdx.x;
    const int tid = threadIdx.x;
    if (tid < 2) {
        const int v = b + tid;
        int lo = 0, hi = NT;
        while (lo < hi) {
            int mid = (lo + hi) >> 1;
            if (seg[mid] < v) lo = mid + 1; else hi = mid;
        }
        s_bounds[tid] = lo;
    }
    __syncthreads();
    const int start = s_bounds[0];
    const int end   = s_bounds[1];
    const int f = tid & 31;
    const int w = tid >> 5;
    float acc = 0.0f;
    for (int r = start + w; r < end; r += 8)
        acc += var_flat[(size_t)r * NF + f];
    red[w][f] = acc;
    __syncthreads();
    if (w == 0) {
        float s = 0.0f;
#pragma unroll
        for (int i = 0; i < 8; i++) s += red[i][f];
        const float cnt = fmaxf((float)(end - start), 1.0f);
        g_means[b * NF + f] = s / cnt;
    }
}

// ---------------- comb GEMM (K=32, fully resident): combined -> packed fp16 (single limb) ----------------
__global__ void __launch_bounds__(256, 2) sgemm_comb(const float* __restrict__ A,
                                                     const float* __restrict__ W,
                                                     const float* __restrict__ bias,
                                                     const float* __restrict__ addend,
                                                     __half* __restrict__ Phi) {
    __shared__ float As[NF][128];
    __shared__ float Bs[NF][128];
    const int bm  = blockIdx.y * 128;
    const int bn  = blockIdx.x * 128;
    const int tid = threadIdx.x;
    const int tx  = tid & 15;
    const int ty  = tid >> 4;

#pragma unroll
    for (int it = 0; it < 4; it++) {
        const int idx = tid + it * 256;
        const int r = idx >> 3;
        const int q = idx & 7;
        const float4 av = *(const float4*)(A + (size_t)(bm + r) * NF + q * 4);
        const float4 wv = *(const float4*)(W + (size_t)(bn + r) * NF + q * 4);
        As[q * 4 + 0][r] = av.x; As[q * 4 + 1][r] = av.y;
        As[q * 4 + 2][r] = av.z; As[q * 4 + 3][r] = av.w;
        Bs[q * 4 + 0][r] = wv.x; Bs[q * 4 + 1][r] = wv.y;
        Bs[q * 4 + 2][r] = wv.z; Bs[q * 4 + 3][r] = wv.w;
    }

    float acc[8][8];
    const float4 bv0 = *(const float4*)(bias + bn + tx * 8);
    const float4 bv1 = *(const float4*)(bias + bn + tx * 8 + 4);
#pragma unroll
    for (int i = 0; i < 8; i++) {
        const int m = bm + ty * 8 + i;
        const float4 a0 = *(const float4*)(addend + (size_t)m * ND + bn + tx * 8);
        const float4 a1 = *(const float4*)(addend + (size_t)m * ND + bn + tx * 8 + 4);
        acc[i][0] = a0.x + bv0.x; acc[i][1] = a0.y + bv0.y;
        acc[i][2] = a0.z + bv0.z; acc[i][3] = a0.w + bv0.w;
        acc[i][4] = a1.x + bv1.x; acc[i][5] = a1.y + bv1.y;
        acc[i][6] = a1.z + bv1.z; acc[i][7] = a1.w + bv1.w;
    }
    __syncthreads();

#pragma unroll
    for (int k = 0; k < NF; k++) {
        float a[8], bb[8];
#pragma unroll
        for (int i = 0; i < 8; i++) a[i] = As[k][ty * 8 + i];
#pragma unroll
        for (int j = 0; j < 8; j++) bb[j] = Bs[k][tx * 8 + j];
#pragma unroll
        for (int i = 0; i < 8; i++)
#pragma unroll
            for (int j = 0; j < 8; j++) acc[i][j] += a[i] * bb[j];
    }

#pragma unroll
    for (int i = 0; i < 8; i++) {
        const int m = bm + ty * 8 + i;
#pragma unroll
        for (int j = 0; j < 8; j += 2) {
            const int n = bn + tx * 8 + j;
            const size_t o = aoff16(m, n, ND) >> 1;
            ((__half2*)Phi)[o] = __floats2half2_rn(acc[i][j], acc[i][j + 1]);
        }
    }
}

// ---------------- weight split into packed fp16 B-fragment layout (rows padded) ----------------
__global__ void __launch_bounds__(256) split_b_kernel(const float* __restrict__ W,
                                                      __half* __restrict__ hi,
                                                      __half* __restrict__ lo,
                                                      int rows, int K, int prows) {
    const size_t idx = (size_t)blockIdx.x * 256 + threadIdx.x;
    const size_t tot = (size_t)prows * (K >> 1);
    if (idx >= tot) return;
    const int n = (int)(idx / (K >> 1));
    const int k = (int)(idx % (K >> 1)) * 2;
    float v0 = 0.0f, v1 = 0.0f;
    if (n < rows) {
        v0 = W[(size_t)n * K + k];
        v1 = W[(size_t)n * K + k + 1];
    }
    __half2 l;
    const __half2 h = split_pair(v0, v1, l);
    const size_t o = boff16(n, k, K) >> 1;
    ((__half2*)hi)[o] = h;
    ((__half2*)lo)[o] = l;
}

// ---------------- fp16 GEMM (NT): A single limb, B 2-limb, 2 products into one f32 acc ----------------
// CTA 128x128, BK=32, 3-stage, occ=2. stage: [A 8KB][B hi 8KB][B lo 8KB] = 24KB
#define STAGE_BYTES 24576

#define LOADC(stg, ck) do {                                                          \
        const uint32_t _d0 = sbase + (uint32_t)(stg) * (uint32_t)STAGE_BYTES;        \
        _Pragma("unroll")                                                            \
        for (int _i = 0; _i < 6; _i++) {                                             \
            const int _u = tid + _i * 256;                                           \
            const __half* _src; uint32_t _dst;                                       \
            if (_u < 512) {                                                          \
                const int _mt = _u >> 6, _rem = _u & 63;                             \
                _src = Ahi                                                           \
                     + ((size_t)(mtile0 + _mt) * KB16 + 2 * (ck)) * 256 + _rem * 8;  \
                _dst = _d0 + _mt * 1024 + _rem * 16;                                 \
            } else {                                                                 \
                const int _v = _u - 512;                                             \
                const int _lb = _v >> 9, _w = _v & 511;                              \
                const int _nt = _w >> 5, _rem = _w & 31;                             \
                _src = (_lb ? Blo : Bhi)                                             \
                     + ((size_t)(ntile0 + _nt) * KB16 + 2 * (ck)) * 128 + _rem * 8;  \
                _dst = _d0 + 8192 + _lb * 8192 + _nt * 512 + _rem * 16;              \
            }                                                                        \
            cp16(_dst, _src);                                                        \
        }                                                                            \
        cp_commit();                                                                 \
    } while (0)

template <int KDIM, bool IS_G1>
__global__ void __launch_bounds__(256, 2) mma_gemm(
    const __half* __restrict__ Ahi,
    const __half* __restrict__ Bhi, const __half* __restrict__ Blo,
    const float* __restrict__ bias,
    float* __restrict__ Crow, __half* __restrict__ Phi) {
    constexpr int KB16 = KDIM / 16;
    constexpr int NCH  = KDIM / 32;
    extern __shared__ __align__(16) char smem[];
    const int tid  = threadIdx.x;
    const int lane = tid & 31;
    const int wrp  = tid >> 5;
    const int warp_m = (wrp & 1) * 64;     // 2 warps along M
    const int warp_n = (wrp >> 1) * 32;    // 4 warps along N
    const int mtW = (wrp & 1) * 4;
    const int ntW = (wrp >> 1) * 4;
    const int bm = blockIdx.y * 128;
    const int bn = blockIdx.x * 128;
    const int mtile0 = blockIdx.y * 8;
    const int ntile0 = blockIdx.x * 16;
    const uint32_t sbase = smem_u32(smem);

    float acc[4][4][4];
#pragma unroll
    for (int a = 0; a < 4; a++)
#pragma unroll
        for (int b = 0; b < 4; b++)
#pragma unroll
            for (int c = 0; c < 4; c++) acc[a][b][c] = 0.0f;

    LOADC(0, 0);
    LOADC(1, 1);

#pragma unroll 1
    for (int ch = 0; ch < NCH; ch++) {
        if (ch + 2 < NCH) {
            LOADC((ch + 2) % 3, ch + 2);
            asm volatile("cp.async.wait_group 2;" ::: "memory");
        } else if (ch + 1 < NCH) {
            asm volatile("cp.async.wait_group 1;" ::: "memory");
        } else {
            asm volatile("cp.async.wait_group 0;" ::: "memory");
        }
        __syncthreads();
        const uint32_t stg = sbase + (uint32_t)(ch % 3) * (uint32_t)STAGE_BYTES;
#pragma unroll
        for (int kt = 0; kt < 2; kt++) {
            uint32_t ah[4][4];
#pragma unroll
            for (int mt = 0; mt < 4; mt++) {
                const uint32_t adr = stg + (mtW + mt) * 1024 + kt * 512 + lane * 16;
                lds128(ah[mt], adr);
            }
            uint32_t bh[4][2], bl[4][2];
#pragma unroll
            for (int nt = 0; nt < 4; nt++) {
                const uint32_t badr = stg + 8192 + (ntW + nt) * 512 + kt * 256 + lane * 8;
                lds64(bh[nt], badr);
                lds64(bl[nt], badr + 8192);
            }
#pragma unroll
            for (int nt = 0; nt < 4; nt++) {
#pragma unroll
                for (int mt = 0; mt < 4; mt++) mma16(acc[mt][nt], ah[mt], bh[nt]);
#pragma unroll
                for (int mt = 0; mt < 4; mt++) mma16(acc[mt][nt], ah[mt], bl[nt]);
            }
        }
        __syncthreads();
    }

    // epilogue
    const int g  = lane >> 2;
    const int tg = lane & 3;
#pragma unroll
    for (int mt = 0; mt < 4; mt++) {
#pragma unroll
        for (int nt = 0; nt < 4; nt++) {
            const int col0 = bn + warp_n + nt * 8 + tg * 2;
            const int row0 = bm + warp_m + mt * 16 + g;
#pragma unroll
            for (int half = 0; half < 2; half++) {
                const int row = row0 + half * 8;
                float v0 = acc[mt][nt][half * 2 + 0];
                float v1 = acc[mt][nt][half * 2 + 1];
                if (IS_G1) {
                    v0 = fmaxf(v0 + __ldg(&bias[col0]), 0.0f);
                    v1 = fmaxf(v1 + __ldg(&bias[col0 + 1]), 0.0f);
                    Crow[(size_t)row * NH + col0]     = v0;
                    Crow[(size_t)row * NH + col0 + 1] = v1;
                    const size_t o = aoff16(row, col0, NH) >> 1;
                    ((__half2*)Phi)[o] = __floats2half2_rn(v0, v1);
                } else {
                    if (col0 < NC)
                        Crow[(size_t)row * NC + col0] = v0 + __ldg(&bias[col0]);
                    if (col0 + 1 < NC)
                        Crow[(size_t)row * NC + col0 + 1] = v1 + __ldg(&bias[col0 + 1]);
                }
            }
        }
    }
}

// ---------------- scalar head ----------------
__global__ void __launch_bounds__(256) scalar_kernel(const float* __restrict__ Ws,
                                                     const float* __restrict__ bs) {
    const int warp = threadIdx.x >> 5;
    const int lane = threadIdx.x & 31;
    const int b = blockIdx.x * 8 + warp;
    const float* hrow = g_hidden + (size_t)b * NH;
    float acc = 0.0f;
    for (int k = lane; k < NH; k += 32) acc += hrow[k] * __ldg(&Ws[k]);
#pragma unroll
    for (int o = 16; o > 0; o >>= 1) acc += __shfl_down_sync(0xffffffffu, acc, o);
    if (lane == 0) g_scalar[b] = acc + bs[0];
}

// ---------------- per-row logsumexp + argmax ----------------
__global__ void __launch_bounds__(256) loss_row_kernel(const int* __restrict__ target) {
    __shared__ float sval[256];
    __shared__ int   sidx[256];
    __shared__ float ssum[256];
    const int b = blockIdx.x;
    const int tid = threadIdx.x;
    const float* row = g_logits + (size_t)b * NC;

    float mval = -3.402823466e38f;
    int midx = 0;
    for (int c = tid; c < NC; c += 256) {
        const float v = row[c];
        if (v > mval) { mval = v; midx = c; }
    }
    sval[tid] = mval; sidx[tid] = midx;
    __syncthreads();
    for (int s = 128; s > 0; s >>= 1) {
        if (tid < s) {
            const float v2 = sval[tid + s];
            const int   i2 = sidx[tid + s];
            if (v2 > sval[tid] || (v2 == sval[tid] && i2 < sidx[tid])) {
                sval[tid] = v2; sidx[tid] = i2;
            }
        }
        __syncthreads();
    }
    const float maxv = sval[0];
    const int   amax = sidx[0];

    float lsum = 0.0f;
    for (int c = tid; c < NC; c += 256) {
        const float d = row[c] - maxv;
        if (d > -20.0f) lsum += __expf(d);
    }
    ssum[tid] = lsum;
    __syncthreads();
    for (int s = 128; s > 0; s >>= 1) {
        if (tid < s) ssum[tid] += ssum[tid + s];
        __syncthreads();
    }
    if (tid == 0) {
        const int t = target[b];
        g_row_lv[b]  = maxv + logf(ssum[0]) - row[t];
        g_row_acc[b] = (amax == t) ? 1.0f : 0.0f;
    }
}

// ---------------- final reduce ----------------
__global__ void __launch_bounds__(1024) final_kernel(const float* __restrict__ target_scalar,
                                                     float* __restrict__ out) {
    __shared__ float s_lv[1024];
    __shared__ float s_ac[1024];
    __shared__ float s_sq[1024];
    const int tid = threadIdx.x;
    float lv = 0.0f, ac = 0.0f, sq = 0.0f;
    for (int b = tid; b < NB; b += 1024) {
        lv += g_row_lv[b];
        ac += g_row_acc[b];
        const float d = g_scalar[b] - target_scalar[b];
        sq += d * d;
    }
    s_lv[tid] = lv; s_ac[tid] = ac; s_sq[tid] = sq;
    __syncthreads();
    for (int s = 512; s > 0; s >>= 1) {
        if (tid < s) {
            s_lv[tid] += s_lv[tid + s];
            s_ac[tid] += s_ac[tid + s];
            s_sq[tid] += s_sq[tid + s];
        }
        __syncthreads();
    }
    if (tid == 0) {
        const float lvm  = s_lv[0] / (float)NB;
        const float sqm  = s_sq[0] / (float)NB;
        const float accm = s_ac[0] / (float)NB;
        out[0] = lvm + sqm;
        out[1] = lvm;
        out[2] = sqm;
        out[3] = accm;
    }
}

// ---------------- launch ----------------
extern "C" void kernel_launch(void* const* d_in, const int* in_sizes, int n_in,
                              void* d_out, int out_size) {
    const float* feature  = (const float*)d_in[0];
    const float* var_flat = (const float*)d_in[1];
    const int*   seg      = (const int*)d_in[2];
    const int*   target_v = (const int*)d_in[3];
    const float* target_s = (const float*)d_in[4];
    const float* Wv       = (const float*)d_in[5];
    const float* bv       = (const float*)d_in[6];
    const float* W1       = (const float*)d_in[7];
    const float* b1       = (const float*)d_in[8];
    const float* W2       = (const float*)d_in[9];
    const float* b2       = (const float*)d_in[10];
    const float* Ws       = (const float*)d_in[11];
    const float* bs       = (const float*)d_in[12];
    float* out = (float*)d_out;

    float *p_means, *p_hid, *p_log;
    __half *p_a1h, *p_w1h, *p_w1l, *p_a2h, *p_w2h, *p_w2l;
    cudaGetSymbolAddress((void**)&p_means, g_means);
    cudaGetSymbolAddress((void**)&p_a1h,   g_a1_hi);
    cudaGetSymbolAddress((void**)&p_w1h,   g_w1_hi);
    cudaGetSymbolAddress((void**)&p_w1l,   g_w1_lo);
    cudaGetSymbolAddress((void**)&p_a2h,   g_a2_hi);
    cudaGetSymbolAddress((void**)&p_w2h,   g_w2_hi);
    cudaGetSymbolAddress((void**)&p_w2l,   g_w2_lo);
    cudaGetSymbolAddress((void**)&p_hid,   g_hidden);
    cudaGetSymbolAddress((void**)&p_log,   g_logits);

    const int SMEM_GEMM = 3 * STAGE_BYTES;  // 73728
    cudaFuncSetAttribute(mma_gemm<1024, true>,
                         cudaFuncAttributeMaxDynamicSharedMemorySize, SMEM_GEMM);
    cudaFuncSetAttribute(mma_gemm<2048, false>,
                         cudaFuncAttributeMaxDynamicSharedMemorySize, SMEM_GEMM);

    // 1) ragged per-segment mean
    seg_mean_kernel<<<NB, 256>>>(var_flat, seg);

    // 2) weight splits into packed fp16 B-fragment layout (2-limb)
    {
        size_t n1 = (size_t)NH * ND / 2;
        split_b_kernel<<<(int)((n1 + 255) / 256), 256>>>(W1, p_w1h, p_w1l, NH, ND, NH);
        size_t n2 = (size_t)NCPAD * NH / 2;
        split_b_kernel<<<(int)((n2 + 255) / 256), 256>>>(W2, p_w2h, p_w2l, NC, NH, NCPAD);
    }

    // 3) combined = means@Wv^T + bv + feature -> packed fp16 A (single limb)
    sgemm_comb<<<dim3(ND / 128, NB / 128), 256>>>(
        p_means, Wv, bv, feature, p_a1h);

    // 4) hidden = relu(combined@W1^T + b1)  [2-product asymmetric split]
    mma_gemm<1024, true><<<dim3(NH / 128, NB / 128), 256, SMEM_GEMM>>>(
        p_a1h, p_w1h, p_w1l, b1, p_hid, p_a2h);

    // 5) logits = hidden@W2^T + b2  [2-product asymmetric split], N guard 1000
    mma_gemm<2048, false><<<dim3(NCPAD / 128, NB / 128), 256, SMEM_GEMM>>>(
        p_a2h, p_w2h, p_w2l, b2, p_log, nullptr);

    // 6) scalar head
    scalar_kernel<<<NB / 8, 256>>>(Ws, bs);

    // 7) per-row softmax stats
    loss_row_kernel<<<NB, 256>>>(target_v);

    // 8) final reduce
    final_kernel<<<1, 1024>>>(target_s, out);
}